// round 7
// baseline (speedup 1.0000x reference)
#include <cuda_runtime.h>
#include <cuda_bf16.h>

#define N_G   4096
#define IMG_W 512
#define TILE  64
#define BLOCK 256
#define NB    512                    // co-resident: regs<=64 -> 4 blk/SM
#define NSUB  512                    // 64 tiles x 8 subtiles (16x32 px, 2 px/thread)
#define NJB   32
#define EXPSCALE (-0.72134752044f)   // -0.5 * log2(e)
#define L99      (-0.014500313f)     // log2(0.99)
#define RTHR_F   (1.0234444f)        // 9.2110/9: dist^2 > RTHR*r^2 -> alpha == 0.01 exactly

__device__ float4 g_geo[N_G];        // px, py, radius, 0
__device__ float4 g_la [N_G];        // px, py, ca*S, cbc*S
__device__ float4 g_lb [N_G];        // cd*S, log2(op), rthr2, r
__device__ float2 g_lc [N_G];        // g, b
__device__ int    g_prank[NJB][N_G];

__device__ float4 t_la[64 * N_G], t_lb[64 * N_G];
__device__ float2 t_lc[64 * N_G];
__device__ int    t_cnt[64];
__device__ int    c3a[64][8];        // per (tile, rank-chunk-of-512) inmask counts
__device__ int    t_ready[64];       // chunks-done counters (tile ready when ==8)

__device__ unsigned g_bar;           // monotonic ticket barrier (replay-safe)
__device__ unsigned g_q;             // phase-4 work queue

__device__ __forceinline__ float ex2f(float x) {
    float y; asm("ex2.approx.f32 %0, %1;" : "=f"(y) : "f"(x)); return y;
}

struct SM {
    float4 n0[BLOCK], n1[BLOCK], n2[BLOCK];  // events
    float  n3[BLOCK];                        // gapP
    int    sF[BLOCK];
    float  sSr[BLOCK], sSg[BLOCK], sSb[BLOCK];
    int    jpos[BLOCK];
    int    wsum[8];
    float  wsf[24];
    float  tailSr, tailSg, tailSb, tailP;
    int    item;
};

__device__ __forceinline__ int scan_bool(bool p, int* wsum, int& tot) {
    __syncthreads();
    const unsigned bits = __ballot_sync(0xffffffffu, p);
    const int lane = threadIdx.x & 31, wd = threadIdx.x >> 5;
    if (lane == 0) wsum[wd] = __popc(bits);
    __syncthreads();
    int off = 0, t = 0;
#pragma unroll
    for (int w = 0; w < 8; w++) { int c = wsum[w]; if (w < wd) off += c; t += c; }
    tot = t;
    return off + __popc(bits & ((1u << lane) - 1u));
}

__device__ __forceinline__ void grid_sync() {
    __syncthreads();
    if (threadIdx.x == 0) {
        __threadfence();
        unsigned v = atomicAdd(&g_bar, 1u);
        unsigned target = (v / NB + 1u) * NB;
        while (*(volatile unsigned*)&g_bar < target) { }
        __threadfence();
    }
    __syncthreads();
}

__global__ void __launch_bounds__(BLOCK, 4)
fused_kernel(const float* __restrict__ pos2d, const float* __restrict__ cov2d,
             const float* __restrict__ opacity, const float* __restrict__ color,
             float* __restrict__ out)
{
    __shared__ SM sm;
    const int tid = threadIdx.x;
    const int bid = blockIdx.x;
    const int lane = tid & 31, wd = tid >> 5;

    // ---------- Phase 1: counters reset + rank partials (FULL grid) ------------
    if (bid == 0) {
        for (int k = tid; k < 64 * 8; k += BLOCK) ((int*)c3a)[k] = 0;
        for (int k = tid; k < 64; k += BLOCK) t_ready[k] = 0;
        if (tid == 0) g_q = 0;
    }
    {
        const int ib = bid >> 5, jb = bid & 31;
        const int i = ib * BLOCK + tid;
        const int j0 = jb * 128;
        const float di = pos2d[i * 3 + 2];
        if (tid < 128) sm.sSr[tid] = pos2d[(j0 + tid) * 3 + 2];
        __syncthreads();
        int cnt = 0;
#pragma unroll 8
        for (int j = 0; j < 128; j++) {
            const float dj = sm.sSr[j];
            cnt += (dj < di) || (dj == di && (j0 + j) < i);
        }
        g_prank[jb][i] = cnt;
    }
    grid_sync();

    // ---------- Phase 2: params + scatter by rank + per-(tile,chunk) counts ----
    if (bid < 16) {
        const int i = bid * BLOCK + tid;
        int rank = 0;
#pragma unroll
        for (int b = 0; b < NJB; b++) rank += g_prank[b][i];

        const float a = cov2d[i * 4 + 0];
        const float b = cov2d[i * 4 + 1];
        const float c = cov2d[i * 4 + 2];
        const float d = cov2d[i * 4 + 3];
        const float trace = a + d;
        const float det   = a * d - b * c;
        const float term2 = 0.5f * sqrtf(fmaxf(trace * trace - 4.0f * det, 0.0f));
        const float radius = 3.0f * sqrtf(fmaxf(0.5f * trace - term2, 0.5f * trace + term2));
        const float inv_det = 1.0f / det;

        const float px = pos2d[i * 3 + 0];
        const float py = pos2d[i * 3 + 1];
        const float lop2 = __log2f(opacity[i]);
        const float cr = fmaxf(color[i * 3 + 0] + 0.5f, 0.0f);
        const float cg = fmaxf(color[i * 3 + 1] + 0.5f, 0.0f);
        const float cb = fmaxf(color[i * 3 + 2] + 0.5f, 0.0f);

        g_geo[rank] = make_float4(px, py, radius, 0.0f);
        g_la [rank] = make_float4(px, py, EXPSCALE * d * inv_det, EXPSCALE * -(b + c) * inv_det);
        g_lb [rank] = make_float4(EXPSCALE * a * inv_det, lop2, RTHR_F * radius * radius, cr);
        g_lc [rank] = make_float2(cg, cb);

        // count into per-(tile, rank-chunk) bins (exact same test as P3)
        const int ch = rank >> 9;
        const int tx0 = max(0, (int)floorf((px - radius) * (1.f / 64.f)) - 1);
        const int tx1 = min(7, (int)floorf((px + radius) * (1.f / 64.f)) + 1);
        const int ty0 = max(0, (int)floorf((py - radius) * (1.f / 64.f)) - 1);
        const int ty1 = min(7, (int)floorf((py + radius) * (1.f / 64.f)) + 1);
        for (int tx = tx0; tx <= tx1; tx++) {
            const float left = (float)(tx * TILE);
            if (!((px + radius >= left) && (px - radius < left + (float)TILE))) continue;
            for (int ty = ty0; ty <= ty1; ty++) {
                const float top = (float)(ty * TILE);
                if ((py + radius >= top) && (py - radius < top + (float)TILE))
                    atomicAdd(&c3a[(tx << 3) | ty][ch], 1);
            }
        }
    }
    grid_sync();

    // ---------- Phase 3: ordered compaction (64 tiles x 8 rank-chunks) ---------
    {
        const int tile = bid >> 3, ch = bid & 7;
        const float left = (float)((tile >> 3) * TILE);
        const float top  = (float)((tile & 7) * TILE);
        int offset = 0, total = 0;
#pragma unroll
        for (int c = 0; c < 8; c++) {
            const int cc = c3a[tile][c];
            if (c < ch) offset += cc;
            total += cc;
        }
        if (ch == 0 && tid == 0) t_cnt[tile] = total;
        int outbase = offset;
#pragma unroll
        for (int r = 0; r < 2; r++) {
            const int g = ch * 512 + r * 256 + tid;
            const float4 geo = g_geo[g];
            const bool v = (geo.x + geo.z >= left) && (geo.x - geo.z < left + (float)TILE) &&
                           (geo.y + geo.z >= top)  && (geo.y - geo.z < top  + (float)TILE);
            int tot;
            const int pos = scan_bool(v, sm.wsum, tot);
            if (v) {
                const int o = tile * N_G + outbase + pos;
                t_la[o] = g_la[g];
                t_lb[o] = g_lb[g];
                t_lc[o] = g_lc[g];
            }
            outbase += tot;
        }
        __syncthreads();
        if (tid == 0) {
            __threadfence();
            atomicAdd(&t_ready[tile], 1);
        }
    }
    // NO grid sync: phase 4 overlaps the tail of phase 3 via t_ready flags.

    // ---------- Phase 4: work-stealing render over 512 subtiles ----------------
    for (;;) {
        __syncthreads();
        if (tid == 0) sm.item = (int)atomicAdd(&g_q, 1u);
        __syncthreads();
        const int sub = sm.item;
        if (sub >= NSUB) break;

        const int ptile = sub >> 3, si = sub & 7;
        // wait until this tile's 8 compaction chunks are published
        if (tid == 0) {
            while (*(volatile int*)&t_ready[ptile] < 8) __nanosleep(64);
            __threadfence();
        }
        __syncthreads();

        const int X0 = (ptile >> 3) * TILE + (si >> 1) * 16;
        const int Y0 = (ptile & 7) * TILE + (si & 1) * 32;
        const float rx0 = (float)X0, rx1 = (float)(X0 + 15);
        const float ry0 = (float)Y0, ry1 = (float)(Y0 + 31);

        const int Xi  = X0 + (tid >> 4);
        const int Yi0 = Y0 + (tid & 15);
        const int Yi1 = Yi0 + 16;
        const float X = (float)Xi, Yf0 = (float)Yi0, Yf1 = (float)Yi1;

        const int cnt = t_cnt[ptile];
        const float4* __restrict__ LA = t_la + ptile * N_G;
        const float4* __restrict__ LB = t_lb + ptile * N_G;
        const float2* __restrict__ LC = t_lc + ptile * N_G;

        float T0 = 1.f, T1 = 1.f;
        float C00 = 0.f, C01 = 0.f, C02 = 0.f, C10 = 0.f, C11 = 0.f, C12 = 0.f;
        bool dead = false;

        for (int c0 = 0; c0 < cnt; c0 += BLOCK) {
            const int L = min(BLOCK, cnt - c0);
            const bool validg = tid < L;
            float4 la = make_float4(0,0,0,0), lb = make_float4(0,0,0,0);
            float2 lc = make_float2(0,0);
            bool isfar = false;
            if (validg) {
                la = LA[c0 + tid]; lb = LB[c0 + tid]; lc = LC[c0 + tid];
                const float cx = fminf(fmaxf(la.x, rx0), rx1);
                const float cy = fminf(fmaxf(la.y, ry0), ry1);
                const float ddx = la.x - cx, ddy = la.y - cy;
                isfar = (ddx * ddx + ddy * ddy) > lb.z;
            }
            int Ftot;
            const int F = scan_bool(isfar, sm.wsum, Ftot);

            // block-exclusive scan of far-weighted colors: w = 0.01*0.99^F
            const float pw = isfar ? 0.01f * ex2f((float)F * L99) : 0.0f;
            const float vr = pw * lb.w, vg = pw * lc.x, vb = pw * lc.y;
            float ir = vr, ig = vg, ibb = vb;
#pragma unroll
            for (int dd = 1; dd < 32; dd <<= 1) {
                const float tr = __shfl_up_sync(0xffffffffu, ir, dd);
                const float tg = __shfl_up_sync(0xffffffffu, ig, dd);
                const float tb = __shfl_up_sync(0xffffffffu, ibb, dd);
                if (lane >= dd) { ir += tr; ig += tg; ibb += tb; }
            }
            __syncthreads();
            if (lane == 31) { sm.wsf[wd*3] = ir; sm.wsf[wd*3+1] = ig; sm.wsf[wd*3+2] = ibb; }
            __syncthreads();
            float offr = 0, offg = 0, offb = 0, totr = 0, totg = 0, totb = 0;
#pragma unroll
            for (int w = 0; w < 8; w++) {
                const float xr = sm.wsf[w*3], xg = sm.wsf[w*3+1], xb = sm.wsf[w*3+2];
                if (w < wd) { offr += xr; offg += xg; offb += xb; }
                totr += xr; totg += xg; totb += xb;
            }
            const float Sr = offr + ir - vr, Sg = offg + ig - vg, Sb = offb + ibb - vb;

            sm.sF[tid] = F; sm.sSr[tid] = Sr; sm.sSg[tid] = Sg; sm.sSb[tid] = Sb;
            const bool isnear = validg && !isfar;
            const int ncnt = L - Ftot;
            const int nidx = tid - F;
            if (isnear) sm.jpos[nidx] = tid;
            __syncthreads();

            if (isnear) {
                float gSr, gSg, gSb, gP;
                if (nidx > 0) {
                    const int pp = sm.jpos[nidx - 1];
                    const float Fp = (float)sm.sF[pp];
                    const float inv = ex2f(-Fp * L99);
                    gSr = (Sr - sm.sSr[pp]) * inv;
                    gSg = (Sg - sm.sSg[pp]) * inv;
                    gSb = (Sb - sm.sSb[pp]) * inv;
                    gP  = ex2f(((float)F - Fp) * L99);
                } else {
                    gSr = Sr; gSg = Sg; gSb = Sb;
                    gP  = ex2f((float)F * L99);
                }
                sm.n0[nidx] = la;
                // folded form: colGP = gP*col
                sm.n1[nidx] = make_float4(lb.x, lb.y, gP * lb.w, gP * lc.x); // cd',lop2,colGPr,colGPg
                sm.n2[nidx] = make_float4(gSr, gSg, gSb, gP * lc.y);         // gapS, colGPb
                sm.n3[nidx] = gP;
            }
            if (tid == 0) {
                if (ncnt > 0) {
                    const int pl = sm.jpos[ncnt - 1];
                    const float Fl = (float)sm.sF[pl];
                    const float inv = ex2f(-Fl * L99);
                    sm.tailSr = (totr - sm.sSr[pl]) * inv;
                    sm.tailSg = (totg - sm.sSg[pl]) * inv;
                    sm.tailSb = (totb - sm.sSb[pl]) * inv;
                    sm.tailP  = ex2f(((float)Ftot - Fl) * L99);
                } else {
                    sm.tailSr = totr; sm.tailSg = totg; sm.tailSb = totb;
                    sm.tailP  = ex2f((float)Ftot * L99);
                }
            }
            __syncthreads();

            // ---- pixel loop: folded composite, ballot every 16 ----
            if (!dead) {
                int t = 0;
                bool alive = true;
                while (alive && t < ncnt) {
                    const int tend = min(t + 16, ncnt);
#pragma unroll 2
                    for (; t < tend; t++) {
                        const float4 f0 = sm.n0[t];
                        const float4 f1 = sm.n1[t];
                        const float4 f2 = sm.n2[t];
                        const float  gP = sm.n3[t];
                        const float dx  = X - f0.x;
                        const float tq  = fmaf(f0.z, dx * dx, f1.y);
                        const float cdx = f0.w * dx;
                        const float dy0 = Yf0 - f0.y, dy1 = Yf1 - f0.y;
                        const float e0 = fmaf(dy0, fmaf(f1.x, dy0, cdx), tq);
                        const float e1 = fmaf(dy1, fmaf(f1.x, dy1, cdx), tq);
                        const float a0 = fminf(fmaxf(ex2f(e0), 0.01f), 0.99f);
                        const float a1 = fminf(fmaxf(ex2f(e1), 0.01f), 0.99f);
                        // C += T*(gapS + a*colGP);  T *= (gP - a*gP)
                        const float t0r = fmaf(a0, f1.z, f2.x), t1r = fmaf(a1, f1.z, f2.x);
                        const float t0g = fmaf(a0, f1.w, f2.y), t1g = fmaf(a1, f1.w, f2.y);
                        const float t0b = fmaf(a0, f2.w, f2.z), t1b = fmaf(a1, f2.w, f2.z);
                        C00 = fmaf(T0, t0r, C00); C01 = fmaf(T0, t0g, C01); C02 = fmaf(T0, t0b, C02);
                        C10 = fmaf(T1, t1r, C10); C11 = fmaf(T1, t1g, C11); C12 = fmaf(T1, t1b, C12);
                        const float u0 = fmaf(-a0, gP, gP), u1 = fmaf(-a1, gP, gP);
                        T0 *= u0; T1 *= u1;
                    }
                    alive = __ballot_sync(0xffffffffu, (T0 >= 1e-7f) || (T1 >= 1e-7f)) != 0;
                }
                C00 = fmaf(T0, sm.tailSr, C00); C01 = fmaf(T0, sm.tailSg, C01); C02 = fmaf(T0, sm.tailSb, C02);
                C10 = fmaf(T1, sm.tailSr, C10); C11 = fmaf(T1, sm.tailSg, C11); C12 = fmaf(T1, sm.tailSb, C12);
                T0 *= sm.tailP; T1 *= sm.tailP;
                if (!alive) dead = true;
            }
            if (__syncthreads_count(dead ? 0 : 1) == 0) break;
        }

        const int ob0 = (Xi * IMG_W + Yi0) * 3;
        out[ob0 + 0] = C00; out[ob0 + 1] = C01; out[ob0 + 2] = C02;
        const int ob1 = (Xi * IMG_W + Yi1) * 3;
        out[ob1 + 0] = C10; out[ob1 + 1] = C11; out[ob1 + 2] = C12;
    }
}

extern "C" void kernel_launch(void* const* d_in, const int* in_sizes, int n_in,
                              void* d_out, int out_size)
{
    const float* pos2d   = (const float*)d_in[0];
    const float* cov2d   = (const float*)d_in[1];
    const float* opacity = (const float*)d_in[2];
    const float* color   = (const float*)d_in[3];
    float* out = (float*)d_out;

    fused_kernel<<<NB, BLOCK>>>(pos2d, cov2d, opacity, color, out);
}

// round 8
// speedup vs baseline: 1.0829x; 1.0829x over previous
#include <cuda_runtime.h>
#include <cuda_bf16.h>

#define N_G   4096
#define IMG_W 512
#define TILE  64
#define BLOCK 256
#define NB    512                    // co-resident: regs<=64 -> 4 blk/SM
#define NSUB  512                    // 64 tiles x 8 subtiles (16x32 px, 2 px/thread)
#define NJB   32
#define EXPSCALE (-0.72134752044f)   // -0.5 * log2(e)
#define INVS     (-1.38629436112f)   // 1/EXPSCALE = -2 ln 2
#define L99      (-0.014500313f)     // log2(0.99)
#define QTHR     (9.21034037f)       // 2 ln 100
#define RTHR_F   (1.0234444f)

__device__ float4 g_geo[N_G];        // px, py, radius, 0
__device__ float4 g_la [N_G];        // px, py, ca*S, cbc*S
__device__ float4 g_lb [N_G];        // cd*S, log2(op), rthr2, r
__device__ float2 g_lc [N_G];        // g, b
__device__ int    g_prank[NJB][N_G];

__device__ float4 t_la[64 * N_G], t_lb[64 * N_G];
__device__ float2 t_lc[64 * N_G];
__device__ int    t_cnt[64];
__device__ int    c3a[64][8];        // per (tile, rank-chunk-of-512) inmask counts
__device__ int    t_ready[64];

__device__ unsigned g_bar;           // monotonic ticket barrier (replay-safe)
__device__ unsigned g_q;             // phase-4 work queue

__device__ __forceinline__ float ex2f(float x) {
    float y; asm("ex2.approx.f32 %0, %1;" : "=f"(y) : "f"(x)); return y;
}

struct SM {
    float4 n0[BLOCK], n1[BLOCK], n2[BLOCK];
    float  n3[BLOCK];
    int    sF[BLOCK];
    float  sSr[BLOCK], sSg[BLOCK], sSb[BLOCK];
    int    jpos[BLOCK];
    int    wsum[8];
    float  wsf[24];
    float  tailSr, tailSg, tailSb, tailP;
    int    item;
};

__device__ __forceinline__ int scan_bool(bool p, int* wsum, int& tot) {
    __syncthreads();
    const unsigned bits = __ballot_sync(0xffffffffu, p);
    const int lane = threadIdx.x & 31, wd = threadIdx.x >> 5;
    if (lane == 0) wsum[wd] = __popc(bits);
    __syncthreads();
    int off = 0, t = 0;
#pragma unroll
    for (int w = 0; w < 8; w++) { int c = wsum[w]; if (w < wd) off += c; t += c; }
    tot = t;
    return off + __popc(bits & ((1u << lane) - 1u));
}

__device__ __forceinline__ void grid_sync() {
    __syncthreads();
    if (threadIdx.x == 0) {
        __threadfence();
        unsigned v = atomicAdd(&g_bar, 1u);
        unsigned target = (v / NB + 1u) * NB;
        while (*(volatile unsigned*)&g_bar < target) { }
        __threadfence();
    }
    __syncthreads();
}

__global__ void __launch_bounds__(BLOCK, 4)
fused_kernel(const float* __restrict__ pos2d, const float* __restrict__ cov2d,
             const float* __restrict__ opacity, const float* __restrict__ color,
             float* __restrict__ out)
{
    __shared__ SM sm;
    const int tid = threadIdx.x;
    const int bid = blockIdx.x;
    const int lane = tid & 31, wd = tid >> 5;

    // ---------- Phase 1: counters reset + rank partials (FULL grid) ------------
    if (bid == 0) {
        for (int k = tid; k < 64 * 8; k += BLOCK) ((int*)c3a)[k] = 0;
        for (int k = tid; k < 64; k += BLOCK) t_ready[k] = 0;
        if (tid == 0) g_q = 0;
    }
    {
        const int ib = bid >> 5, jb = bid & 31;
        const int i = ib * BLOCK + tid;
        const int j0 = jb * 128;
        const float di = pos2d[i * 3 + 2];
        if (tid < 128) sm.sSr[tid] = pos2d[(j0 + tid) * 3 + 2];
        __syncthreads();
        int cnt = 0;
#pragma unroll 8
        for (int j = 0; j < 128; j++) {
            const float dj = sm.sSr[j];
            cnt += (dj < di) || (dj == di && (j0 + j) < i);
        }
        g_prank[jb][i] = cnt;
    }
    grid_sync();

    // ---------- Phase 2: params + scatter by rank + per-(tile,chunk) counts ----
    if (bid < 16) {
        const int i = bid * BLOCK + tid;
        int rank = 0;
#pragma unroll
        for (int b = 0; b < NJB; b++) rank += g_prank[b][i];

        const float a = cov2d[i * 4 + 0];
        const float b = cov2d[i * 4 + 1];
        const float c = cov2d[i * 4 + 2];
        const float d = cov2d[i * 4 + 3];
        const float trace = a + d;
        const float det   = a * d - b * c;
        const float term2 = 0.5f * sqrtf(fmaxf(trace * trace - 4.0f * det, 0.0f));
        const float radius = 3.0f * sqrtf(fmaxf(0.5f * trace - term2, 0.5f * trace + term2));
        const float inv_det = 1.0f / det;

        const float px = pos2d[i * 3 + 0];
        const float py = pos2d[i * 3 + 1];
        const float lop2 = __log2f(opacity[i]);
        const float cr = fmaxf(color[i * 3 + 0] + 0.5f, 0.0f);
        const float cg = fmaxf(color[i * 3 + 1] + 0.5f, 0.0f);
        const float cb = fmaxf(color[i * 3 + 2] + 0.5f, 0.0f);

        g_geo[rank] = make_float4(px, py, radius, 0.0f);
        g_la [rank] = make_float4(px, py, EXPSCALE * d * inv_det, EXPSCALE * -(b + c) * inv_det);
        g_lb [rank] = make_float4(EXPSCALE * a * inv_det, lop2, RTHR_F * radius * radius, cr);
        g_lc [rank] = make_float2(cg, cb);

        const int ch = rank >> 9;
        const int tx0 = max(0, (int)floorf((px - radius) * (1.f / 64.f)) - 1);
        const int tx1 = min(7, (int)floorf((px + radius) * (1.f / 64.f)) + 1);
        const int ty0 = max(0, (int)floorf((py - radius) * (1.f / 64.f)) - 1);
        const int ty1 = min(7, (int)floorf((py + radius) * (1.f / 64.f)) + 1);
        for (int tx = tx0; tx <= tx1; tx++) {
            const float left = (float)(tx * TILE);
            if (!((px + radius >= left) && (px - radius < left + (float)TILE))) continue;
            for (int ty = ty0; ty <= ty1; ty++) {
                const float top = (float)(ty * TILE);
                if ((py + radius >= top) && (py - radius < top + (float)TILE))
                    atomicAdd(&c3a[(tx << 3) | ty][ch], 1);
            }
        }
    }
    grid_sync();

    // ---------- Phase 3: ordered compaction (64 tiles x 8 rank-chunks) ---------
    {
        const int tile = bid >> 3, ch = bid & 7;
        const float left = (float)((tile >> 3) * TILE);
        const float top  = (float)((tile & 7) * TILE);
        int offset = 0, total = 0;
#pragma unroll
        for (int c = 0; c < 8; c++) {
            const int cc = c3a[tile][c];
            if (c < ch) offset += cc;
            total += cc;
        }
        if (ch == 0 && tid == 0) t_cnt[tile] = total;
        int outbase = offset;
#pragma unroll
        for (int r = 0; r < 2; r++) {
            const int g = ch * 512 + r * 256 + tid;
            const float4 geo = g_geo[g];
            const bool v = (geo.x + geo.z >= left) && (geo.x - geo.z < left + (float)TILE) &&
                           (geo.y + geo.z >= top)  && (geo.y - geo.z < top  + (float)TILE);
            int tot;
            const int pos = scan_bool(v, sm.wsum, tot);
            if (v) {
                const int o = tile * N_G + outbase + pos;
                t_la[o] = g_la[g];
                t_lb[o] = g_lb[g];
                t_lc[o] = g_lc[g];
            }
            outbase += tot;
        }
        __syncthreads();
        if (tid == 0) {
            __threadfence();
            atomicAdd(&t_ready[tile], 1);
        }
    }

    // ---------- Phase 4: work-stealing render over 512 subtiles ----------------
    for (;;) {
        __syncthreads();
        if (tid == 0) sm.item = (int)atomicAdd(&g_q, 1u);
        __syncthreads();
        const int sub = sm.item;
        if (sub >= NSUB) break;

        const int ptile = sub >> 3, si = sub & 7;
        if (tid == 0) {
            while (*(volatile int*)&t_ready[ptile] < 8) __nanosleep(64);
            __threadfence();
        }
        __syncthreads();

        const int X0 = (ptile >> 3) * TILE + (si >> 1) * 16;
        const int Y0 = (ptile & 7) * TILE + (si & 1) * 32;
        const float rx0 = (float)X0, rx1 = (float)(X0 + 15);
        const float ry0 = (float)Y0, ry1 = (float)(Y0 + 31);

        const int Xi  = X0 + (tid >> 4);
        const int Yi0 = Y0 + (tid & 15);
        const int Yi1 = Yi0 + 16;
        const float X = (float)Xi, Yf0 = (float)Yi0, Yf1 = (float)Yi1;

        const int cnt = t_cnt[ptile];
        const float4* __restrict__ LA = t_la + ptile * N_G;
        const float4* __restrict__ LB = t_lb + ptile * N_G;
        const float2* __restrict__ LC = t_lc + ptile * N_G;

        float T0 = 1.f, T1 = 1.f;
        float C00 = 0.f, C01 = 0.f, C02 = 0.f, C10 = 0.f, C11 = 0.f, C12 = 0.f;
        bool dead = false;

        for (int c0 = 0; c0 < cnt; c0 += BLOCK) {
            const int L = min(BLOCK, cnt - c0);
            const bool validg = tid < L;
            float4 la = make_float4(0,0,0,0), lb = make_float4(0,0,0,0);
            float2 lc = make_float2(0,0);
            bool isfar = false;
            if (validg) {
                la = LA[c0 + tid]; lb = LB[c0 + tid]; lc = LC[c0 + tid];
                // exact conic min over the subtile rect, opacity-adjusted threshold:
                // far <=> qmin > 2ln100 + 2ln(op)  (then alpha == 0.01 for every pixel)
                const float Aq = la.z * INVS, Bq = la.w * INVS, Cq = lb.x * INVS;
                const float dxlo = rx0 - la.x, dxhi = rx1 - la.x;
                const float dylo = ry0 - la.y, dyhi = ry1 - la.y;
                const bool inside = (dxlo <= 0.f) && (dxhi >= 0.f) &&
                                    (dylo <= 0.f) && (dyhi >= 0.f);
                float qm = 0.0f;
                if (!inside) {
                    const float hc = -0.5f * Bq / Cq;   // argmin dy for fixed dx
                    const float ha = -0.5f * Bq / Aq;   // argmin dx for fixed dy
                    float dys = fminf(fmaxf(hc * dxlo, dylo), dyhi);
                    qm = fmaf(fmaf(Bq, dys, Aq * dxlo), dxlo, Cq * dys * dys);
                    dys = fminf(fmaxf(hc * dxhi, dylo), dyhi);
                    qm = fminf(qm, fmaf(fmaf(Bq, dys, Aq * dxhi), dxhi, Cq * dys * dys));
                    float dxs = fminf(fmaxf(ha * dylo, dxlo), dxhi);
                    qm = fminf(qm, fmaf(fmaf(Bq, dxs, Cq * dylo), dylo, Aq * dxs * dxs));
                    dxs = fminf(fmaxf(ha * dyhi, dxlo), dxhi);
                    qm = fminf(qm, fmaf(fmaf(Bq, dxs, Cq * dyhi), dyhi, Aq * dxs * dxs));
                }
                isfar = qm > fmaf(-INVS, lb.y, QTHR);   // QTHR + 2ln2*log2(op)
            }
            int Ftot;
            const int F = scan_bool(isfar, sm.wsum, Ftot);

            const float pw = isfar ? 0.01f * ex2f((float)F * L99) : 0.0f;
            const float vr = pw * lb.w, vg = pw * lc.x, vb = pw * lc.y;
            float ir = vr, ig = vg, ibb = vb;
#pragma unroll
            for (int dd = 1; dd < 32; dd <<= 1) {
                const float tr = __shfl_up_sync(0xffffffffu, ir, dd);
                const float tg = __shfl_up_sync(0xffffffffu, ig, dd);
                const float tb = __shfl_up_sync(0xffffffffu, ibb, dd);
                if (lane >= dd) { ir += tr; ig += tg; ibb += tb; }
            }
            __syncthreads();
            if (lane == 31) { sm.wsf[wd*3] = ir; sm.wsf[wd*3+1] = ig; sm.wsf[wd*3+2] = ibb; }
            __syncthreads();
            float offr = 0, offg = 0, offb = 0, totr = 0, totg = 0, totb = 0;
#pragma unroll
            for (int w = 0; w < 8; w++) {
                const float xr = sm.wsf[w*3], xg = sm.wsf[w*3+1], xb = sm.wsf[w*3+2];
                if (w < wd) { offr += xr; offg += xg; offb += xb; }
                totr += xr; totg += xg; totb += xb;
            }
            const float Sr = offr + ir - vr, Sg = offg + ig - vg, Sb = offb + ibb - vb;

            sm.sF[tid] = F; sm.sSr[tid] = Sr; sm.sSg[tid] = Sg; sm.sSb[tid] = Sb;
            const bool isnear = validg && !isfar;
            const int ncnt = L - Ftot;
            const int nidx = tid - F;
            if (isnear) sm.jpos[nidx] = tid;
            __syncthreads();

            if (isnear) {
                float gSr, gSg, gSb, gP;
                if (nidx > 0) {
                    const int pp = sm.jpos[nidx - 1];
                    const float Fp = (float)sm.sF[pp];
                    const float inv = ex2f(-Fp * L99);
                    gSr = (Sr - sm.sSr[pp]) * inv;
                    gSg = (Sg - sm.sSg[pp]) * inv;
                    gSb = (Sb - sm.sSb[pp]) * inv;
                    gP  = ex2f(((float)F - Fp) * L99);
                } else {
                    gSr = Sr; gSg = Sg; gSb = Sb;
                    gP  = ex2f((float)F * L99);
                }
                sm.n0[nidx] = la;
                sm.n1[nidx] = make_float4(lb.x, lb.y, gP * lb.w, gP * lc.x);
                sm.n2[nidx] = make_float4(gSr, gSg, gSb, gP * lc.y);
                sm.n3[nidx] = gP;
            }
            if (tid == 0) {
                if (ncnt > 0) {
                    const int pl = sm.jpos[ncnt - 1];
                    const float Fl = (float)sm.sF[pl];
                    const float inv = ex2f(-Fl * L99);
                    sm.tailSr = (totr - sm.sSr[pl]) * inv;
                    sm.tailSg = (totg - sm.sSg[pl]) * inv;
                    sm.tailSb = (totb - sm.sSb[pl]) * inv;
                    sm.tailP  = ex2f(((float)Ftot - Fl) * L99);
                } else {
                    sm.tailSr = totr; sm.tailSg = totg; sm.tailSb = totb;
                    sm.tailP  = ex2f((float)Ftot * L99);
                }
            }
            __syncthreads();

            if (!dead) {
                int t = 0;
                bool alive = true;
                while (alive && t < ncnt) {
                    const int tend = min(t + 16, ncnt);
#pragma unroll 2
                    for (; t < tend; t++) {
                        const float4 f0 = sm.n0[t];
                        const float4 f1 = sm.n1[t];
                        const float4 f2 = sm.n2[t];
                        const float  gP = sm.n3[t];
                        const float dx  = X - f0.x;
                        const float tq  = fmaf(f0.z, dx * dx, f1.y);
                        const float cdx = f0.w * dx;
                        const float dy0 = Yf0 - f0.y, dy1 = Yf1 - f0.y;
                        const float e0 = fmaf(dy0, fmaf(f1.x, dy0, cdx), tq);
                        const float e1 = fmaf(dy1, fmaf(f1.x, dy1, cdx), tq);
                        const float a0 = fminf(fmaxf(ex2f(e0), 0.01f), 0.99f);
                        const float a1 = fminf(fmaxf(ex2f(e1), 0.01f), 0.99f);
                        const float t0r = fmaf(a0, f1.z, f2.x), t1r = fmaf(a1, f1.z, f2.x);
                        const float t0g = fmaf(a0, f1.w, f2.y), t1g = fmaf(a1, f1.w, f2.y);
                        const float t0b = fmaf(a0, f2.w, f2.z), t1b = fmaf(a1, f2.w, f2.z);
                        C00 = fmaf(T0, t0r, C00); C01 = fmaf(T0, t0g, C01); C02 = fmaf(T0, t0b, C02);
                        C10 = fmaf(T1, t1r, C10); C11 = fmaf(T1, t1g, C11); C12 = fmaf(T1, t1b, C12);
                        const float u0 = fmaf(-a0, gP, gP), u1 = fmaf(-a1, gP, gP);
                        T0 *= u0; T1 *= u1;
                    }
                    alive = __ballot_sync(0xffffffffu, (T0 >= 1e-7f) || (T1 >= 1e-7f)) != 0;
                }
                C00 = fmaf(T0, sm.tailSr, C00); C01 = fmaf(T0, sm.tailSg, C01); C02 = fmaf(T0, sm.tailSb, C02);
                C10 = fmaf(T1, sm.tailSr, C10); C11 = fmaf(T1, sm.tailSg, C11); C12 = fmaf(T1, sm.tailSb, C12);
                T0 *= sm.tailP; T1 *= sm.tailP;
                if (!alive) dead = true;
            }
            if (__syncthreads_count(dead ? 0 : 1) == 0) break;
        }

        const int ob0 = (Xi * IMG_W + Yi0) * 3;
        out[ob0 + 0] = C00; out[ob0 + 1] = C01; out[ob0 + 2] = C02;
        const int ob1 = (Xi * IMG_W + Yi1) * 3;
        out[ob1 + 0] = C10; out[ob1 + 1] = C11; out[ob1 + 2] = C12;
    }
}

extern "C" void kernel_launch(void* const* d_in, const int* in_sizes, int n_in,
                              void* d_out, int out_size)
{
    const float* pos2d   = (const float*)d_in[0];
    const float* cov2d   = (const float*)d_in[1];
    const float* opacity = (const float*)d_in[2];
    const float* color   = (const float*)d_in[3];
    float* out = (float*)d_out;

    fused_kernel<<<NB, BLOCK>>>(pos2d, cov2d, opacity, color, out);
}